// round 14
// baseline (speedup 1.0000x reference)
#include <cuda_runtime.h>
#include <cuda_bf16.h>
#include <math.h>
#include <cstdint>

#define NLAYERS 6
#define DMODEL  512
#define NHEADS  8
#define DHEAD   64
#define BATCH   4
#define SEQ     1024
#define TOKENS  (BATCH*SEQ)      // 4096
#define DFF     2048
#define LN_EPS  1e-5f
#define NQKV    (3*DMODEL)       // 1536

typedef __nv_bfloat16 bf16;

// ---------------- scratch (device globals; no allocation allowed) ----------------
__device__ __align__(16) float g_x  [TOKENS*DMODEL];
__device__ __align__(16) float g_y  [TOKENS*DMODEL];

__device__ __align__(16) bf16 g_xh[TOKENS*DMODEL],  g_xl[TOKENS*DMODEL];
__device__ __align__(16) bf16 g_qh[TOKENS*DMODEL],  g_ql[TOKENS*DMODEL];
__device__ __align__(16) bf16 g_kh[TOKENS*DMODEL],  g_kl[TOKENS*DMODEL];
__device__ __align__(16) bf16 g_vTh[TOKENS*DMODEL], g_vTl[TOKENS*DMODEL];   // [512][4096]
__device__ __align__(16) bf16 g_ah[TOKENS*DMODEL],  g_al[TOKENS*DMODEL];
__device__ __align__(16) bf16 g_h1h[TOKENS*DFF],    g_h1l[TOKENS*DFF];

// transposed bf16 weights
__device__ __align__(16) bf16 g_wqkvTh[NLAYERS*NQKV*DMODEL], g_wqkvTl[NLAYERS*NQKV*DMODEL];
__device__ __align__(16) bf16 g_woTh[NLAYERS*DMODEL*DMODEL], g_woTl[NLAYERS*DMODEL*DMODEL];
__device__ __align__(16) bf16 g_w1Th[NLAYERS*DMODEL*DFF],    g_w1Tl[NLAYERS*DMODEL*DFF];
__device__ __align__(16) bf16 g_w2Th[NLAYERS*DMODEL*DFF],    g_w2Tl[NLAYERS*DMODEL*DFF];
__device__ __align__(16) float g_bqkv[NLAYERS*NQKV];

// ---------------- helpers ----------------
__device__ __forceinline__ void split_bf16(float v, bf16& h, bf16& l) {
    h = __float2bfloat16_rn(v);
    l = __float2bfloat16_rn(v - __bfloat162float(h));
}

__device__ __forceinline__ void cpasync16(unsigned saddr, const void* g) {
    asm volatile("cp.async.cg.shared.global [%0], [%1], 16;\n" :: "r"(saddr), "l"(g));
}

__device__ __forceinline__ float block_sum(float v) {
    __shared__ float s[32];
    #pragma unroll
    for (int o = 16; o; o >>= 1) v += __shfl_xor_sync(0xffffffffu, v, o);
    int lane = threadIdx.x & 31, w = threadIdx.x >> 5;
    if (lane == 0) s[w] = v;
    __syncthreads();
    int nw = blockDim.x >> 5;
    v = (threadIdx.x < (unsigned)nw) ? s[threadIdx.x] : 0.f;
    if (w == 0) {
        #pragma unroll
        for (int o = 16; o; o >>= 1) v += __shfl_xor_sync(0xffffffffu, v, o);
        if (lane == 0) s[0] = v;
    }
    __syncthreads();
    v = s[0];
    __syncthreads();
    return v;
}

// ---------------- embedding + positional encoding (+hi/lo) ----------------
__global__ void embed_k(const int* __restrict__ tok, const float* __restrict__ emb,
                        float* __restrict__ x, bf16* __restrict__ xh, bf16* __restrict__ xl) {
    long long row = blockIdx.x;
    int s = (int)(row & (SEQ - 1));
    int tk = tok[row];
    int t = threadIdx.x;
    #pragma unroll
    for (int j = 0; j < 4; j++) {
        int i = t * 4 + j;
        float freq = (float)exp(-(double)i * (9.210340371976184 / (double)DMODEL));
        float ang = (float)s * freq;
        float pe = (i & 1) ? cosf(ang) : sinf(ang);
        float v = emb[(long long)tk * DMODEL + i] + pe;
        x[row * DMODEL + i] = v;
        bf16 h, l; split_bf16(v, h, l);
        xh[row * DMODEL + i] = h;
        xl[row * DMODEL + i] = l;
    }
}

// ------- weight transpose + bf16 split: W[K][N] -> T[N][K] -------
__global__ void wconv_k(const float* __restrict__ W, bf16* __restrict__ Th,
                        bf16* __restrict__ Tl, int N, int K,
                        long long wstride, long long dstride) {
    __shared__ float tile[32][33];
    W  += (long long)blockIdx.z * wstride;
    Th += (long long)blockIdx.z * dstride;
    Tl += (long long)blockIdx.z * dstride;
    int n0 = blockIdx.x * 32, k0 = blockIdx.y * 32;
    int tx = threadIdx.x, ty = threadIdx.y;          // 32 x 8
    #pragma unroll
    for (int i = 0; i < 4; i++)
        tile[ty + 8 * i][tx] = W[(long long)(k0 + ty + 8 * i) * N + n0 + tx];
    __syncthreads();
    #pragma unroll
    for (int i = 0; i < 4; i++) {
        float v = tile[tx][ty + 8 * i];
        bf16 h, l; split_bf16(v, h, l);
        long long o = (long long)(n0 + ty + 8 * i) * K + k0 + tx;
        Th[o] = h; Tl[o] = l;
    }
}

// ------- fused Wq/Wk/Wv/Wo transpose+split: 24 [512][512] matrices in ONE launch -------
__global__ void wconv4_k(const float* __restrict__ Wq, const float* __restrict__ Wk,
                         const float* __restrict__ Wv, const float* __restrict__ Wo,
                         bf16* __restrict__ qkvTh, bf16* __restrict__ qkvTl,
                         bf16* __restrict__ oTh,   bf16* __restrict__ oTl) {
    __shared__ float tile[32][33];
    const long long WS = (long long)DMODEL * DMODEL;
    const long long QS = (long long)NQKV * DMODEL;
    int z = blockIdx.z;                // 0..23
    int widx = z / NLAYERS, layer = z - widx * NLAYERS;
    const float* W = (widx == 0) ? Wq : (widx == 1) ? Wk : (widx == 2) ? Wv : Wo;
    W += layer * WS;
    bf16 *Th, *Tl;
    if (widx < 3) { Th = qkvTh + layer * QS + widx * WS; Tl = qkvTl + layer * QS + widx * WS; }
    else          { Th = oTh + layer * WS;               Tl = oTl + layer * WS; }
    int n0 = blockIdx.x * 32, k0 = blockIdx.y * 32;
    int tx = threadIdx.x, ty = threadIdx.y;          // 32 x 8
    #pragma unroll
    for (int i = 0; i < 4; i++)
        tile[ty + 8 * i][tx] = W[(long long)(k0 + ty + 8 * i) * DMODEL + n0 + tx];
    __syncthreads();
    #pragma unroll
    for (int i = 0; i < 4; i++) {
        float v = tile[tx][ty + 8 * i];
        bf16 h, l; split_bf16(v, h, l);
        long long o = (long long)(n0 + ty + 8 * i) * DMODEL + k0 + tx;
        Th[o] = h; Tl[o] = l;
    }
}

// ---- merge q,k,v biases into one [1536] per layer ----
__global__ void bmerge_k(const float* __restrict__ bq, const float* __restrict__ bk,
                         const float* __restrict__ bv, float* __restrict__ o) {
    int l = blockIdx.x, t = threadIdx.x;   // 512 threads
    o[l * NQKV + t]            = bq[l * DMODEL + t];
    o[l * NQKV + DMODEL + t]   = bk[l * DMODEL + t];
    o[l * NQKV + 2*DMODEL + t] = bv[l * DMODEL + t];
}

#define MMA_BF16(c, a0,a1,a2,a3, b0,b1)                                          \
    asm volatile("mma.sync.aligned.m16n8k16.row.col.f32.bf16.bf16.f32 "          \
                 "{%0,%1,%2,%3}, {%4,%5,%6,%7}, {%8,%9}, {%0,%1,%2,%3};"         \
                 : "+f"(c[0]), "+f"(c[1]), "+f"(c[2]), "+f"(c[3])                \
                 : "r"(a0), "r"(a1), "r"(a2), "r"(a3), "r"(b0), "r"(b1))

// ---------------- tensor-core GEMM (bf16 hi/lo triple, fp32 acc) ----------------
// 128 threads, 4 warps, 2x2 warp grid, warp tile 64x64, BM=BN=128.
// Double-buffered cp.async, scalar-LDS fragment loads, XOR-swizzled 16-word rows
// (64 KB total smem -> 3 CTAs/SM).
// swizzle: phys word = row*16 + (col ^ (((row>>1)&3)*4)); row bases are multiples
// of 8 so per-lane sw = ((lane>>3)&3)*4, and rows r/r+8 share sw (+128 words).
// OUT: 0 = fp32 Cf[ldc]; 1 = bf16 hi/lo Ch/Cl[ldc];
//      3 = QKV routing by n0: seg0->Ch/Cl [m][512], seg1->Dh/Dl [m][512],
//          seg2->Eh/El transposed [n][TOKENS]
template<int OUT, bool RELU>
__global__ __launch_bounds__(128, 3) void gemm_k(
    const bf16* __restrict__ Ah, const bf16* __restrict__ Al, long long lda,
    const bf16* __restrict__ Bh, const bf16* __restrict__ Bl, long long ldb,
    float* __restrict__ Cf, bf16* __restrict__ Ch, bf16* __restrict__ Cl,
    bf16* __restrict__ Dh, bf16* __restrict__ Dl,
    bf16* __restrict__ Eh, bf16* __restrict__ El,
    long long ldc, const float* __restrict__ bias, int K)
{
    extern __shared__ uint32_t sm[];
    const int AW = 128 * 16;                           // words per matrix (2048)
    const int SS = 4 * AW;                             // words per stage (8192 = 32 KB)

    const int m0 = blockIdx.y * 128;
    const int n0 = blockIdx.x * 128;
    const int t = threadIdx.x;
    const int lane = t & 31, w = t >> 5;
    const int wm = w >> 1, wn = w & 1;                 // 2 x 2 warp grid

    const unsigned sb = (unsigned)__cvta_generic_to_shared(sm);

    float acc[4][8][4];
    #pragma unroll
    for (int i = 0; i < 4; i++)
        #pragma unroll
        for (int j = 0; j < 8; j++)
            #pragma unroll
            for (int r = 0; r < 4; r++) acc[i][j][r] = 0.f;

    const int nk = K / 32;

    auto load_stage = [&](int ks, int st) {
        const unsigned base = sb + st * SS * 4;
        const int k0 = ks * 32;
        #pragma unroll
        for (int i = 0; i < 4; i++) {
            int id = i * 128 + t;
            int row = id >> 2, cb = id & 3;
            long long go = (long long)(m0 + row) * lda + k0 + cb * 8;
            unsigned so = row * 64 + ((cb * 16) ^ (((row >> 1) & 3) * 16));
            cpasync16(base + so, Ah + go);
            cpasync16(base + AW * 4 + so, Al + go);
        }
        #pragma unroll
        for (int i = 0; i < 4; i++) {
            int id = i * 128 + t;
            int row = id >> 2, cb = id & 3;
            long long go = (long long)(n0 + row) * ldb + k0 + cb * 8;
            unsigned so = row * 64 + ((cb * 16) ^ (((row >> 1) & 3) * 16));
            cpasync16(base + 2 * AW * 4 + so, Bh + go);
            cpasync16(base + 3 * AW * 4 + so, Bl + go);
        }
        asm volatile("cp.async.commit_group;");
    };

    load_stage(0, 0);

    const int swz = ((lane >> 3) & 3) * 4;             // per-lane swizzle (row-base mult of 8)
    const int lq  = lane >> 2;                         // quad row
    const int lc  = lane & 3;                          // k-word within half

    for (int ks = 0; ks < nk; ks++) {
        if (ks + 1 < nk) {
            load_stage(ks + 1, (ks + 1) & 1);
            asm volatile("cp.async.wait_group 1;" ::: "memory");
        } else {
            asm volatile("cp.async.wait_group 0;" ::: "memory");
        }
        __syncthreads();

        const uint32_t* Ash = sm + (ks & 1) * SS;
        const uint32_t* Asl = Ash + AW;
        const uint32_t* Bsh = Ash + 2 * AW;
        const uint32_t* Bsl = Ash + 3 * AW;

        #pragma unroll
        for (int s = 0; s < 2; s++) {
            const int kw = s * 8;
            const int c1 = (kw + lc) ^ swz;
            const int c2 = (kw + 4 + lc) ^ swz;
            uint32_t bh[8][2], bl[8][2];
            #pragma unroll
            for (int j = 0; j < 8; j++) {
                int rb = (wn * 64 + j * 8 + lq) * 16;
                bh[j][0] = Bsh[rb + c1]; bh[j][1] = Bsh[rb + c2];
                bl[j][0] = Bsl[rb + c1]; bl[j][1] = Bsl[rb + c2];
            }
            #pragma unroll
            for (int i = 0; i < 4; i++) {
                int ra = (wm * 64 + i * 16 + lq) * 16;
                uint32_t ah0 = Ash[ra + c1],       ah1 = Ash[ra + 128 + c1];
                uint32_t ah2 = Ash[ra + c2],       ah3 = Ash[ra + 128 + c2];
                uint32_t al0 = Asl[ra + c1],       al1 = Asl[ra + 128 + c1];
                uint32_t al2 = Asl[ra + c2],       al3 = Asl[ra + 128 + c2];
                #pragma unroll
                for (int j = 0; j < 8; j++) {
                    MMA_BF16(acc[i][j], ah0, ah1, ah2, ah3, bh[j][0], bh[j][1]);
                    MMA_BF16(acc[i][j], ah0, ah1, ah2, ah3, bl[j][0], bl[j][1]);
                    MMA_BF16(acc[i][j], al0, al1, al2, al3, bh[j][0], bh[j][1]);
                }
            }
        }
        __syncthreads();
    }

    // ---- epilogue ----
    int seg = 0;
    bf16 *Xh = Ch, *Xl = Cl;
    if (OUT == 3) {
        seg = n0 >> 9;
        Xh = (seg == 0) ? Ch : (seg == 1) ? Dh : Eh;
        Xl = (seg == 0) ? Cl : (seg == 1) ? Dl : El;
    }

    #pragma unroll
    for (int i = 0; i < 4; i++) {
        int r0 = m0 + wm * 64 + i * 16 + (lane >> 2);
        int r1 = r0 + 8;
        #pragma unroll
        for (int j = 0; j < 8; j++) {
            int n = n0 + wn * 64 + j * 8 + 2 * (lane & 3);
            float b0v = bias[n], b1v = bias[n + 1];
            float v00 = acc[i][j][0] + b0v;
            float v01 = acc[i][j][1] + b1v;
            float v10 = acc[i][j][2] + b0v;
            float v11 = acc[i][j][3] + b1v;
            if (RELU) {
                v00 = fmaxf(v00, 0.f); v01 = fmaxf(v01, 0.f);
                v10 = fmaxf(v10, 0.f); v11 = fmaxf(v11, 0.f);
            }
            if (OUT == 0) {
                *(float2*)(Cf + (long long)r0 * ldc + n) = make_float2(v00, v01);
                *(float2*)(Cf + (long long)r1 * ldc + n) = make_float2(v10, v11);
            } else if (OUT == 1) {
                __nv_bfloat162 h, l;
                split_bf16(v00, h.x, l.x); split_bf16(v01, h.y, l.y);
                *(__nv_bfloat162*)(Ch + (long long)r0 * ldc + n) = h;
                *(__nv_bfloat162*)(Cl + (long long)r0 * ldc + n) = l;
                split_bf16(v10, h.x, l.x); split_bf16(v11, h.y, l.y);
                *(__nv_bfloat162*)(Ch + (long long)r1 * ldc + n) = h;
                *(__nv_bfloat162*)(Cl + (long long)r1 * ldc + n) = l;
            } else { // OUT == 3
                int nl = n & 511;
                if (seg < 2) {
                    __nv_bfloat162 h, l;
                    split_bf16(v00, h.x, l.x); split_bf16(v01, h.y, l.y);
                    *(__nv_bfloat162*)(Xh + (long long)r0 * DMODEL + nl) = h;
                    *(__nv_bfloat162*)(Xl + (long long)r0 * DMODEL + nl) = l;
                    split_bf16(v10, h.x, l.x); split_bf16(v11, h.y, l.y);
                    *(__nv_bfloat162*)(Xh + (long long)r1 * DMODEL + nl) = h;
                    *(__nv_bfloat162*)(Xl + (long long)r1 * DMODEL + nl) = l;
                } else {
                    bf16 h, l;
                    split_bf16(v00, h, l); Xh[(long long)nl * TOKENS + r0] = h; Xl[(long long)nl * TOKENS + r0] = l;
                    split_bf16(v01, h, l); Xh[(long long)(nl + 1) * TOKENS + r0] = h; Xl[(long long)(nl + 1) * TOKENS + r0] = l;
                    split_bf16(v10, h, l); Xh[(long long)nl * TOKENS + r1] = h; Xl[(long long)nl * TOKENS + r1] = l;
                    split_bf16(v11, h, l); Xh[(long long)(nl + 1) * TOKENS + r1] = h; Xl[(long long)(nl + 1) * TOKENS + r1] = l;
                }
            }
        }
    }
}

#define GSMEM (2 * 4 * 128 * 16 * 4)   // 65536 B: 2 stages x 4 matrices x 128x16 words

// ---------------- fused flash attention ----------------
#define FQW (64 * 36)
#define FMW (64 * 36)
#define FSMEM ((2 * FQW + 8 * FMW) * 4)   // 92160 B

__global__ __launch_bounds__(128) void flash_k(
    const bf16* __restrict__ qh_, const bf16* __restrict__ ql_,
    const bf16* __restrict__ kh_, const bf16* __restrict__ kl_,
    const bf16* __restrict__ vTh_, const bf16* __restrict__ vTl_,
    bf16* __restrict__ oh_, bf16* __restrict__ ol_)
{
    extern __shared__ uint32_t sm[];
    const int qt = blockIdx.x;
    const int bh = blockIdx.y;
    const int b = bh >> 3, h = bh & 7;
    const int q0 = qt * 64;
    const int t = threadIdx.x, lane = t & 31, w = t >> 5;
    const unsigned sb = (unsigned)__cvta_generic_to_shared(sm);

    #pragma unroll
    for (int i = 0; i < 4; i++) {
        int id = i * 128 + t;
        int r = id >> 3, cb = id & 7;
        long long gq = ((long long)(b * SEQ + q0 + r)) * DMODEL + h * DHEAD + cb * 8;
        unsigned so = r * 144 + cb * 16;
        cpasync16(sb + so, qh_ + gq);
        cpasync16(sb + FQW * 4 + so, ql_ + gq);
    }
    asm volatile("cp.async.commit_group;");

    auto load_stage = [&](int ti, int st) {
        const unsigned base = sb + (2 * FQW + st * 4 * FMW) * 4;
        const int t0 = ti * 64;
        #pragma unroll
        for (int i = 0; i < 4; i++) {
            int id = i * 128 + t;
            int r = id >> 3, cb = id & 7;
            unsigned so = r * 144 + cb * 16;
            long long gk = ((long long)(b * SEQ + t0 + r)) * DMODEL + h * DHEAD + cb * 8;
            cpasync16(base + so, kh_ + gk);
            cpasync16(base + FMW * 4 + so, kl_ + gk);
            long long gv = ((long long)(h * DHEAD + r)) * TOKENS + b * SEQ + t0 + cb * 8;
            cpasync16(base + 2 * FMW * 4 + so, vTh_ + gv);
            cpasync16(base + 3 * FMW * 4 + so, vTl_ + gv);
        }
        asm volatile("cp.async.commit_group;");
    };

    load_stage(0, 0);
    asm volatile("cp.async.wait_group 0;" ::: "memory");
    __syncthreads();

    uint32_t qfh[4][4], qfl[4][4];
    {
        const uint32_t* Qh = sm;
        const uint32_t* Ql = sm + FQW;
        int rw = (w * 16 + (lane >> 2)) * 36;
        #pragma unroll
        for (int ks = 0; ks < 4; ks++) {
            int idx = rw + ks * 8 + (lane & 3);
            qfh[ks][0] = Qh[idx];       qfh[ks][1] = Qh[idx + 288];
            qfh[ks][2] = Qh[idx + 4];   qfh[ks][3] = Qh[idx + 292];
            qfl[ks][0] = Ql[idx];       qfl[ks][1] = Ql[idx + 288];
            qfl[ks][2] = Ql[idx + 4];   qfl[ks][3] = Ql[idx + 292];
        }
    }

    float acc_o[8][4];
    #pragma unroll
    for (int j = 0; j < 8; j++)
        #pragma unroll
        for (int r = 0; r < 4; r++) acc_o[j][r] = 0.f;
    float m0 = -1e30f, m1 = -1e30f, l0 = 0.f, l1 = 0.f;

    const int NT = SEQ / 64;

    for (int ti = 0; ti < NT; ti++) {
        if (ti + 1 < NT) load_stage(ti + 1, (ti + 1) & 1);

        const uint32_t* Kh = sm + 2 * FQW + (ti & 1) * 4 * FMW;
        const uint32_t* Kl = Kh + FMW;
        const uint32_t* Vh = Kh + 2 * FMW;
        const uint32_t* Vl = Kh + 3 * FMW;

        float s_[8][4];
        #pragma unroll
        for (int j = 0; j < 8; j++)
            #pragma unroll
            for (int r = 0; r < 4; r++) s_[j][r] = 0.f;

        #pragma unroll
        for (int ks = 0; ks < 4; ks++) {
            #pragma unroll
            for (int j = 0; j < 8; j++) {
                int bi = (j * 8 + (lane >> 2)) * 36 + ks * 8 + (lane & 3);
                uint32_t kb0 = Kh[bi], kb1 = Kh[bi + 4];
                uint32_t kl0 = Kl[bi], kl1 = Kl[bi + 4];
                MMA_BF16(s_[j], qfh[ks][0], qfh[ks][1], qfh[ks][2], qfh[ks][3], kb0, kb1);
                MMA_BF16(s_[j], qfh[ks][0], qfh[ks][1], qfh[ks][2], qfh[ks][3], kl0, kl1);
                MMA_BF16(s_[j], qfl[ks][0], qfl[ks][1], qfl[ks][2], qfl[ks][3], kb0, kb1);
            }
        }

        float tm0 = -1e30f, tm1 = -1e30f;
        #pragma unroll
        for (int j = 0; j < 8; j++) {
            s_[j][0] *= 0.125f; s_[j][1] *= 0.125f; s_[j][2] *= 0.125f; s_[j][3] *= 0.125f;
            tm0 = fmaxf(tm0, fmaxf(s_[j][0], s_[j][1]));
            tm1 = fmaxf(tm1, fmaxf(s_[j][2], s_[j][3]));
        }
        tm0 = fmaxf(tm0, __shfl_xor_sync(0xffffffffu, tm0, 1));
        tm0 = fmaxf(tm0, __shfl_xor_sync(0xffffffffu, tm0, 2));
        tm1 = fmaxf(tm1, __shfl_xor_sync(0xffffffffu, tm1, 1));
        tm1 = fmaxf(tm1, __shfl_xor_sync(0xffffffffu, tm1, 2));
        float mn0 = fmaxf(m0, tm0), mn1 = fmaxf(m1, tm1);
        float f0 = __expf(m0 - mn0), f1 = __expf(m1 - mn1);
        m0 = mn0; m1 = mn1;

        float sum0 = 0.f, sum1 = 0.f;
        #pragma unroll
        for (int j = 0; j < 8; j++) {
            s_[j][0] = __expf(s_[j][0] - mn0);
            s_[j][1] = __expf(s_[j][1] - mn0);
            s_[j][2] = __expf(s_[j][2] - mn1);
            s_[j][3] = __expf(s_[j][3] - mn1);
            sum0 += s_[j][0] + s_[j][1];
            sum1 += s_[j][2] + s_[j][3];
        }
        sum0 += __shfl_xor_sync(0xffffffffu, sum0, 1);
        sum0 += __shfl_xor_sync(0xffffffffu, sum0, 2);
        sum1 += __shfl_xor_sync(0xffffffffu, sum1, 1);
        sum1 += __shfl_xor_sync(0xffffffffu, sum1, 2);
        l0 = l0 * f0 + sum0;
        l1 = l1 * f1 + sum1;

        #pragma unroll
        for (int j = 0; j < 8; j++) {
            acc_o[j][0] *= f0; acc_o[j][1] *= f0;
            acc_o[j][2] *= f1; acc_o[j][3] *= f1;
        }

        #pragma unroll
        for (int ts = 0; ts < 4; ts++) {
            uint32_t pah[4], pal[4];
            #pragma unroll
            for (int half = 0; half < 2; half++) {
                const float* p = s_[2 * ts + half];
                __nv_bfloat162 h2, l2;
                split_bf16(p[0], h2.x, l2.x); split_bf16(p[1], h2.y, l2.y);
                pah[half ? 2 : 0] = *(uint32_t*)&h2;
                pal[half ? 2 : 0] = *(uint32_t*)&l2;
                split_bf16(p[2], h2.x, l2.x); split_bf16(p[3], h2.y, l2.y);
                pah[half ? 3 : 1] = *(uint32_t*)&h2;
                pal[half ? 3 : 1] = *(uint32_t*)&l2;
            }
            #pragma unroll
            for (int jd = 0; jd < 8; jd++) {
                int bi = (jd * 8 + (lane >> 2)) * 36 + ts * 8 + (lane & 3);
                uint32_t vb0 = Vh[bi], vb1 = Vh[bi + 4];
                uint32_t vl0 = Vl[bi], vl1 = Vl[bi + 4];
                MMA_BF16(acc_o[jd], pah[0], pah[1], pah[2], pah[3], vb0, vb1);
                MMA_BF16(acc_o[jd], pah[0], pah[1], pah[2], pah[3], vl0, vl1);
                MMA_BF16(acc_o[jd], pal[0], pal[1], pal[2], pal[3], vb0, vb1);
            }
        }

        if (ti + 1 < NT) { asm volatile("cp.async.wait_group 0;" ::: "memory"); }
        __syncthreads();
    }

    float i0 = 1.f / l0, i1 = 1.f / l1;
    int r0 = q0 + w * 16 + (lane >> 2);
    int r1 = r0 + 8;
    long long base0 = ((long long)bh * SEQ + r0) * DHEAD;
    long long base1 = ((long long)bh * SEQ + r1) * DHEAD;
    #pragma unroll
    for (int jd = 0; jd < 8; jd++) {
        int c = jd * 8 + 2 * (lane & 3);
        __nv_bfloat162 h2, l2;
        split_bf16(acc_o[jd][0] * i0, h2.x, l2.x);
        split_bf16(acc_o[jd][1] * i0, h2.y, l2.y);
        *(__nv_bfloat162*)(oh_ + base0 + c) = h2;
        *(__nv_bfloat162*)(ol_ + base0 + c) = l2;
        split_bf16(acc_o[jd][2] * i1, h2.x, l2.x);
        split_bf16(acc_o[jd][3] * i1, h2.y, l2.y);
        *(__nv_bfloat162*)(oh_ + base1 + c) = h2;
        *(__nv_bfloat162*)(ol_ + base1 + c) = l2;
    }
}

// ---------------- fused residual add + LayerNorm (optionally emits hi/lo) ----------
template<bool WH>
__global__ void addln_k(const float* __restrict__ a, const float* __restrict__ b,
                        const float* __restrict__ g, const float* __restrict__ be,
                        float* __restrict__ o, bf16* __restrict__ oh, bf16* __restrict__ ol) {
    long long row = blockIdx.x;
    int t = threadIdx.x;
    float4 av = *(const float4*)(a + row * DMODEL + t * 4);
    float4 bv = *(const float4*)(b + row * DMODEL + t * 4);
    float x0 = av.x + bv.x, x1 = av.y + bv.y, x2 = av.z + bv.z, x3 = av.w + bv.w;
    float m = block_sum(x0 + x1 + x2 + x3) * (1.f / DMODEL);
    float d0 = x0 - m, d1 = x1 - m, d2 = x2 - m, d3 = x3 - m;
    float var = block_sum(d0 * d0 + d1 * d1 + d2 * d2 + d3 * d3) * (1.f / DMODEL);
    float r = rsqrtf(var + LN_EPS);
    float4 gv = *(const float4*)(g + t * 4);
    float4 ev = *(const float4*)(be + t * 4);
    float4 ov;
    ov.x = d0 * r * gv.x + ev.x;
    ov.y = d1 * r * gv.y + ev.y;
    ov.z = d2 * r * gv.z + ev.z;
    ov.w = d3 * r * gv.w + ev.w;
    *(float4*)(o + row * DMODEL + t * 4) = ov;
    if (WH) {
        __nv_bfloat162 h0, l0, h1, l1;
        split_bf16(ov.x, h0.x, l0.x); split_bf16(ov.y, h0.y, l0.y);
        split_bf16(ov.z, h1.x, l1.x); split_bf16(ov.w, h1.y, l1.y);
        long long off = row * DMODEL + t * 4;
        *(__nv_bfloat162*)(oh + off) = h0; *(__nv_bfloat162*)(oh + off + 2) = h1;
        *(__nv_bfloat162*)(ol + off) = l0; *(__nv_bfloat162*)(ol + off + 2) = l1;
    }
}

// ---------------- launch ----------------
extern "C" void kernel_launch(void* const* d_in, const int* in_sizes, int n_in,
                              void* d_out, int out_size)
{
    const int*   tok = (const int*)d_in[0];
    const float* emb = (const float*)d_in[1];
    const float* Wq = (const float*)d_in[2],  *bq = (const float*)d_in[3];
    const float* Wk = (const float*)d_in[4],  *bk = (const float*)d_in[5];
    const float* Wv = (const float*)d_in[6],  *bv = (const float*)d_in[7];
    const float* Wo = (const float*)d_in[8],  *bo = (const float*)d_in[9];
    const float* W1 = (const float*)d_in[10], *b1 = (const float*)d_in[11];
    const float* W2 = (const float*)d_in[12], *b2 = (const float*)d_in[13];
    const float* lg = (const float*)d_in[14], *lb = (const float*)d_in[15];
    float* out = (float*)d_out;

    float *x, *y, *bqkv;
    bf16 *xh, *xl, *qh, *ql, *kh, *kl, *vTh, *vTl, *ah, *al, *h1h, *h1l;
    bf16 *wqkvTh, *wqkvTl, *woTh, *woTl, *w1Th, *w1Tl, *w2Th, *w2Tl;
    cudaGetSymbolAddress((void**)&x,   g_x);
    cudaGetSymbolAddress((void**)&y,   g_y);
    cudaGetSymbolAddress((void**)&bqkv, g_bqkv);
    cudaGetSymbolAddress((void**)&xh,  g_xh);   cudaGetSymbolAddress((void**)&xl,  g_xl);
    cudaGetSymbolAddress((void**)&qh,  g_qh);   cudaGetSymbolAddress((void**)&ql,  g_ql);
    cudaGetSymbolAddress((void**)&kh,  g_kh);   cudaGetSymbolAddress((void**)&kl,  g_kl);
    cudaGetSymbolAddress((void**)&vTh, g_vTh);  cudaGetSymbolAddress((void**)&vTl, g_vTl);
    cudaGetSymbolAddress((void**)&ah,  g_ah);   cudaGetSymbolAddress((void**)&al,  g_al);
    cudaGetSymbolAddress((void**)&h1h, g_h1h);  cudaGetSymbolAddress((void**)&h1l, g_h1l);
    cudaGetSymbolAddress((void**)&wqkvTh, g_wqkvTh); cudaGetSymbolAddress((void**)&wqkvTl, g_wqkvTl);
    cudaGetSymbolAddress((void**)&woTh, g_woTh); cudaGetSymbolAddress((void**)&woTl, g_woTl);
    cudaGetSymbolAddress((void**)&w1Th, g_w1Th); cudaGetSymbolAddress((void**)&w1Tl, g_w1Tl);
    cudaGetSymbolAddress((void**)&w2Th, g_w2Th); cudaGetSymbolAddress((void**)&w2Tl, g_w2Tl);

    cudaFuncSetAttribute(gemm_k<0,false>, cudaFuncAttributeMaxDynamicSharedMemorySize, GSMEM);
    cudaFuncSetAttribute(gemm_k<1,true >, cudaFuncAttributeMaxDynamicSharedMemorySize, GSMEM);
    cudaFuncSetAttribute(gemm_k<3,false>, cudaFuncAttributeMaxDynamicSharedMemorySize, GSMEM);
    cudaFuncSetAttribute(flash_k, cudaFuncAttributeMaxDynamicSharedMemorySize, FSMEM);

    // ---- setup: exactly 5 launches so launch index 5 = first QKV GEMM (ncu -s 5) ----
    dim3 cb(32, 8);
    wconv4_k<<<dim3(16, 16, 4 * NLAYERS), cb>>>(Wq, Wk, Wv, Wo, wqkvTh, wqkvTl, woTh, woTl);
    wconv_k<<<dim3(64, 16, NLAYERS), cb>>>(W1, w1Th, w1Tl, DFF, DMODEL,
                                           (long long)DMODEL*DFF, (long long)DMODEL*DFF);
    wconv_k<<<dim3(16, 64, NLAYERS), cb>>>(W2, w2Th, w2Tl, DMODEL, DFF,
                                           (long long)DMODEL*DFF, (long long)DMODEL*DFF);
    bmerge_k<<<NLAYERS, DMODEL>>>(bq, bk, bv, bqkv);
    embed_k<<<TOKENS, 128>>>(tok, emb, x, xh, xl);

    for (int i = 0; i < NLAYERS; i++) {
        long long woff = (long long)i * DMODEL * DMODEL;
        long long qoff = (long long)i * NQKV * DMODEL;
        long long foff = (long long)i * DMODEL * DFF;
        const float* boi = bo + (long long)i * DMODEL;
        const float* b1i = b1 + (long long)i * DFF;
        const float* b2i = b2 + (long long)i * DMODEL;
        const float* lgi = lg + (long long)i * DMODEL;
        const float* lbi = lb + (long long)i * DMODEL;

        // merged QKV projection: N=1536; Q,K row-major; V transposed
        gemm_k<3,false><<<dim3(12, 32), 128, GSMEM>>>(
            xh, xl, DMODEL, wqkvTh + qoff, wqkvTl + qoff, DMODEL,
            nullptr, qh, ql, kh, kl, vTh, vTl, DMODEL,
            bqkv + (long long)i * NQKV, DMODEL);

        // fused attention -> bf16 hi/lo attn in bugged layout
        flash_k<<<dim3(16, 32), 128, FSMEM>>>(qh, ql, kh, kl, vTh, vTl, ah, al);

        // O projection -> fp32 y
        gemm_k<0,false><<<dim3(4, 32), 128, GSMEM>>>(
            ah, al, DMODEL, woTh + woff, woTl + woff, DMODEL,
            y, nullptr, nullptr, nullptr, nullptr, nullptr, nullptr, DMODEL,
            boi, DMODEL);

        addln_k<true><<<TOKENS, 128>>>(x, y, lgi, lbi, x, xh, xl);

        // FFN1 (relu) -> bf16 hi/lo [4096][2048]
        gemm_k<1,true><<<dim3(16, 32), 128, GSMEM>>>(
            xh, xl, DMODEL, w1Th + foff, w1Tl + foff, DMODEL,
            nullptr, h1h, h1l, nullptr, nullptr, nullptr, nullptr, DFF,
            b1i, DMODEL);

        // FFN2 -> fp32 y
        gemm_k<0,false><<<dim3(4, 32), 128, GSMEM>>>(
            h1h, h1l, DFF, w2Th + foff, w2Tl + foff, DFF,
            y, nullptr, nullptr, nullptr, nullptr, nullptr, nullptr, DMODEL,
            b2i, DFF);

        if (i == NLAYERS - 1)
            addln_k<false><<<TOKENS, 128>>>(x, y, lgi, lbi, out, nullptr, nullptr);
        else
            addln_k<true><<<TOKENS, 128>>>(x, y, lgi, lbi, x, xh, xl);
    }
}

// round 15
// speedup vs baseline: 1.1260x; 1.1260x over previous
#include <cuda_runtime.h>
#include <cuda_bf16.h>
#include <math.h>
#include <cstdint>

#define NLAYERS 6
#define DMODEL  512
#define NHEADS  8
#define DHEAD   64
#define BATCH   4
#define SEQ     1024
#define TOKENS  (BATCH*SEQ)      // 4096
#define DFF     2048
#define LN_EPS  1e-5f
#define NQKV    (3*DMODEL)       // 1536

typedef __nv_bfloat16 bf16;

// ---------------- scratch (device globals; no allocation allowed) ----------------
__device__ __align__(16) float g_x  [TOKENS*DMODEL];
__device__ __align__(16) float g_y  [TOKENS*DMODEL];

__device__ __align__(16) bf16 g_xh[TOKENS*DMODEL],  g_xl[TOKENS*DMODEL];
__device__ __align__(16) bf16 g_qh[TOKENS*DMODEL],  g_ql[TOKENS*DMODEL];
__device__ __align__(16) bf16 g_kh[TOKENS*DMODEL],  g_kl[TOKENS*DMODEL];
__device__ __align__(16) bf16 g_vTh[TOKENS*DMODEL], g_vTl[TOKENS*DMODEL];   // [512][4096]
__device__ __align__(16) bf16 g_ah[TOKENS*DMODEL],  g_al[TOKENS*DMODEL];
__device__ __align__(16) bf16 g_h1h[TOKENS*DFF],    g_h1l[TOKENS*DFF];

// transposed bf16 weights
__device__ __align__(16) bf16 g_wqkvTh[NLAYERS*NQKV*DMODEL], g_wqkvTl[NLAYERS*NQKV*DMODEL];
__device__ __align__(16) bf16 g_woTh[NLAYERS*DMODEL*DMODEL], g_woTl[NLAYERS*DMODEL*DMODEL];
__device__ __align__(16) bf16 g_w1Th[NLAYERS*DMODEL*DFF],    g_w1Tl[NLAYERS*DMODEL*DFF];
__device__ __align__(16) bf16 g_w2Th[NLAYERS*DMODEL*DFF],    g_w2Tl[NLAYERS*DMODEL*DFF];
__device__ __align__(16) float g_bqkv[NLAYERS*NQKV];

// ---------------- helpers ----------------
__device__ __forceinline__ void split_bf16(float v, bf16& h, bf16& l) {
    h = __float2bfloat16_rn(v);
    l = __float2bfloat16_rn(v - __bfloat162float(h));
}

__device__ __forceinline__ void cpasync16(unsigned saddr, const void* g) {
    asm volatile("cp.async.cg.shared.global [%0], [%1], 16;\n" :: "r"(saddr), "l"(g));
}

__device__ __forceinline__ float block_sum(float v) {
    __shared__ float s[32];
    #pragma unroll
    for (int o = 16; o; o >>= 1) v += __shfl_xor_sync(0xffffffffu, v, o);
    int lane = threadIdx.x & 31, w = threadIdx.x >> 5;
    if (lane == 0) s[w] = v;
    __syncthreads();
    int nw = blockDim.x >> 5;
    v = (threadIdx.x < (unsigned)nw) ? s[threadIdx.x] : 0.f;
    if (w == 0) {
        #pragma unroll
        for (int o = 16; o; o >>= 1) v += __shfl_xor_sync(0xffffffffu, v, o);
        if (lane == 0) s[0] = v;
    }
    __syncthreads();
    v = s[0];
    __syncthreads();
    return v;
}

// ---------------- embedding + positional encoding (+hi/lo) ----------------
__global__ void embed_k(const int* __restrict__ tok, const float* __restrict__ emb,
                        float* __restrict__ x, bf16* __restrict__ xh, bf16* __restrict__ xl) {
    long long row = blockIdx.x;
    int s = (int)(row & (SEQ - 1));
    int tk = tok[row];
    int t = threadIdx.x;
    #pragma unroll
    for (int j = 0; j < 4; j++) {
        int i = t * 4 + j;
        float freq = (float)exp(-(double)i * (9.210340371976184 / (double)DMODEL));
        float ang = (float)s * freq;
        float pe = (i & 1) ? cosf(ang) : sinf(ang);
        float v = emb[(long long)tk * DMODEL + i] + pe;
        x[row * DMODEL + i] = v;
        bf16 h, l; split_bf16(v, h, l);
        xh[row * DMODEL + i] = h;
        xl[row * DMODEL + i] = l;
    }
}

// ------- weight transpose + bf16 split: W[K][N] -> T[N][K] -------
__global__ void wconv_k(const float* __restrict__ W, bf16* __restrict__ Th,
                        bf16* __restrict__ Tl, int N, int K,
                        long long wstride, long long dstride) {
    __shared__ float tile[32][33];
    W  += (long long)blockIdx.z * wstride;
    Th += (long long)blockIdx.z * dstride;
    Tl += (long long)blockIdx.z * dstride;
    int n0 = blockIdx.x * 32, k0 = blockIdx.y * 32;
    int tx = threadIdx.x, ty = threadIdx.y;          // 32 x 8
    #pragma unroll
    for (int i = 0; i < 4; i++)
        tile[ty + 8 * i][tx] = W[(long long)(k0 + ty + 8 * i) * N + n0 + tx];
    __syncthreads();
    #pragma unroll
    for (int i = 0; i < 4; i++) {
        float v = tile[tx][ty + 8 * i];
        bf16 h, l; split_bf16(v, h, l);
        long long o = (long long)(n0 + ty + 8 * i) * K + k0 + tx;
        Th[o] = h; Tl[o] = l;
    }
}

// ------- fused Wq/Wk/Wv/Wo transpose+split: 24 [512][512] matrices in ONE launch -------
__global__ void wconv4_k(const float* __restrict__ Wq, const float* __restrict__ Wk,
                         const float* __restrict__ Wv, const float* __restrict__ Wo,
                         bf16* __restrict__ qkvTh, bf16* __restrict__ qkvTl,
                         bf16* __restrict__ oTh,   bf16* __restrict__ oTl) {
    __shared__ float tile[32][33];
    const long long WS = (long long)DMODEL * DMODEL;
    const long long QS = (long long)NQKV * DMODEL;
    int z = blockIdx.z;                // 0..23
    int widx = z / NLAYERS, layer = z - widx * NLAYERS;
    const float* W = (widx == 0) ? Wq : (widx == 1) ? Wk : (widx == 2) ? Wv : Wo;
    W += layer * WS;
    bf16 *Th, *Tl;
    if (widx < 3) { Th = qkvTh + layer * QS + widx * WS; Tl = qkvTl + layer * QS + widx * WS; }
    else          { Th = oTh + layer * WS;               Tl = oTl + layer * WS; }
    int n0 = blockIdx.x * 32, k0 = blockIdx.y * 32;
    int tx = threadIdx.x, ty = threadIdx.y;          // 32 x 8
    #pragma unroll
    for (int i = 0; i < 4; i++)
        tile[ty + 8 * i][tx] = W[(long long)(k0 + ty + 8 * i) * DMODEL + n0 + tx];
    __syncthreads();
    #pragma unroll
    for (int i = 0; i < 4; i++) {
        float v = tile[tx][ty + 8 * i];
        bf16 h, l; split_bf16(v, h, l);
        long long o = (long long)(n0 + ty + 8 * i) * DMODEL + k0 + tx;
        Th[o] = h; Tl[o] = l;
    }
}

// ---- merge q,k,v biases into one [1536] per layer ----
__global__ void bmerge_k(const float* __restrict__ bq, const float* __restrict__ bk,
                         const float* __restrict__ bv, float* __restrict__ o) {
    int l = blockIdx.x, t = threadIdx.x;   // 512 threads
    o[l * NQKV + t]            = bq[l * DMODEL + t];
    o[l * NQKV + DMODEL + t]   = bk[l * DMODEL + t];
    o[l * NQKV + 2*DMODEL + t] = bv[l * DMODEL + t];
}

#define MMA_BF16(c, a0,a1,a2,a3, b0,b1)                                          \
    asm volatile("mma.sync.aligned.m16n8k16.row.col.f32.bf16.bf16.f32 "          \
                 "{%0,%1,%2,%3}, {%4,%5,%6,%7}, {%8,%9}, {%0,%1,%2,%3};"         \
                 : "+f"(c[0]), "+f"(c[1]), "+f"(c[2]), "+f"(c[3])                \
                 : "r"(a0), "r"(a1), "r"(a2), "r"(a3), "r"(b0), "r"(b1))

// ---------------- tensor-core GEMM (bf16 hi/lo triple, fp32 acc) ----------------
// R11-frozen config: 128 threads, 2x2 warp grid, warp tile 64x64, BM=BN=128,
// 20-word padded rows, double-buffered cp.async, scalar-LDS fragment loads.
// OUT: 0 = fp32 Cf[ldc]; 1 = bf16 hi/lo Ch/Cl[ldc];
//      3 = QKV routing by n0: seg0->Ch/Cl [m][512], seg1->Dh/Dl [m][512],
//          seg2->Eh/El transposed [n][TOKENS]
template<int OUT, bool RELU>
__global__ __launch_bounds__(128) void gemm_k(
    const bf16* __restrict__ Ah, const bf16* __restrict__ Al, long long lda,
    const bf16* __restrict__ Bh, const bf16* __restrict__ Bl, long long ldb,
    float* __restrict__ Cf, bf16* __restrict__ Ch, bf16* __restrict__ Cl,
    bf16* __restrict__ Dh, bf16* __restrict__ Dl,
    bf16* __restrict__ Eh, bf16* __restrict__ El,
    long long ldc, const float* __restrict__ bias, int K)
{
    extern __shared__ uint32_t sm[];
    const int AW = 128 * 20, BW = 128 * 20;
    const int SS = 2 * AW + 2 * BW;

    const int m0 = blockIdx.y * 128;
    const int n0 = blockIdx.x * 128;
    const int t = threadIdx.x;
    const int lane = t & 31, w = t >> 5;
    const int wm = w >> 1, wn = w & 1;

    const unsigned sb = (unsigned)__cvta_generic_to_shared(sm);

    float acc[4][8][4];
    #pragma unroll
    for (int i = 0; i < 4; i++)
        #pragma unroll
        for (int j = 0; j < 8; j++)
            #pragma unroll
            for (int r = 0; r < 4; r++) acc[i][j][r] = 0.f;

    const int nk = K / 32;

    auto load_stage = [&](int ks, int st) {
        const unsigned base = sb + st * SS * 4;
        const int k0 = ks * 32;
        #pragma unroll
        for (int i = 0; i < 4; i++) {
            int id = i * 128 + t;
            int row = id >> 2, cb = id & 3;
            long long go = (long long)(m0 + row) * lda + k0 + cb * 8;
            unsigned so = row * 80 + cb * 16;
            cpasync16(base + so, Ah + go);
            cpasync16(base + AW * 4 + so, Al + go);
        }
        #pragma unroll
        for (int i = 0; i < 4; i++) {
            int id = i * 128 + t;
            int row = id >> 2, cb = id & 3;
            long long go = (long long)(n0 + row) * ldb + k0 + cb * 8;
            unsigned so = row * 80 + cb * 16;
            cpasync16(base + 2 * AW * 4 + so, Bh + go);
            cpasync16(base + (2 * AW + BW) * 4 + so, Bl + go);
        }
        asm volatile("cp.async.commit_group;");
    };

    load_stage(0, 0);

    for (int ks = 0; ks < nk; ks++) {
        if (ks + 1 < nk) {
            load_stage(ks + 1, (ks + 1) & 1);
            asm volatile("cp.async.wait_group 1;" ::: "memory");
        } else {
            asm volatile("cp.async.wait_group 0;" ::: "memory");
        }
        __syncthreads();

        const uint32_t* Ash = sm + (ks & 1) * SS;
        const uint32_t* Asl = Ash + AW;
        const uint32_t* Bsh = Ash + 2 * AW;
        const uint32_t* Bsl = Ash + 2 * AW + BW;

        #pragma unroll
        for (int s = 0; s < 2; s++) {
            const int kw = s * 8;
            uint32_t bh[8][2], bl[8][2];
            #pragma unroll
            for (int j = 0; j < 8; j++) {
                int idx = (wn * 64 + j * 8 + (lane >> 2)) * 20 + kw + (lane & 3);
                bh[j][0] = Bsh[idx]; bh[j][1] = Bsh[idx + 4];
                bl[j][0] = Bsl[idx]; bl[j][1] = Bsl[idx + 4];
            }
            #pragma unroll
            for (int i = 0; i < 4; i++) {
                int idx = (wm * 64 + i * 16 + (lane >> 2)) * 20 + kw + (lane & 3);
                uint32_t ah0 = Ash[idx],       ah1 = Ash[idx + 160];
                uint32_t ah2 = Ash[idx + 4],   ah3 = Ash[idx + 164];
                uint32_t al0 = Asl[idx],       al1 = Asl[idx + 160];
                uint32_t al2 = Asl[idx + 4],   al3 = Asl[idx + 164];
                #pragma unroll
                for (int j = 0; j < 8; j++) {
                    MMA_BF16(acc[i][j], ah0, ah1, ah2, ah3, bh[j][0], bh[j][1]);
                    MMA_BF16(acc[i][j], ah0, ah1, ah2, ah3, bl[j][0], bl[j][1]);
                    MMA_BF16(acc[i][j], al0, al1, al2, al3, bh[j][0], bh[j][1]);
                }
            }
        }
        __syncthreads();
    }

    // ---- epilogue ----
    int seg = 0;
    bf16 *Xh = Ch, *Xl = Cl;
    if (OUT == 3) {
        seg = n0 >> 9;
        Xh = (seg == 0) ? Ch : (seg == 1) ? Dh : Eh;
        Xl = (seg == 0) ? Cl : (seg == 1) ? Dl : El;
    }

    #pragma unroll
    for (int i = 0; i < 4; i++) {
        int r0 = m0 + wm * 64 + i * 16 + (lane >> 2);
        int r1 = r0 + 8;
        #pragma unroll
        for (int j = 0; j < 8; j++) {
            int n = n0 + wn * 64 + j * 8 + 2 * (lane & 3);
            float b0v = bias[n], b1v = bias[n + 1];
            float v00 = acc[i][j][0] + b0v;
            float v01 = acc[i][j][1] + b1v;
            float v10 = acc[i][j][2] + b0v;
            float v11 = acc[i][j][3] + b1v;
            if (RELU) {
                v00 = fmaxf(v00, 0.f); v01 = fmaxf(v01, 0.f);
                v10 = fmaxf(v10, 0.f); v11 = fmaxf(v11, 0.f);
            }
            if (OUT == 0) {
                *(float2*)(Cf + (long long)r0 * ldc + n) = make_float2(v00, v01);
                *(float2*)(Cf + (long long)r1 * ldc + n) = make_float2(v10, v11);
            } else if (OUT == 1) {
                __nv_bfloat162 h, l;
                split_bf16(v00, h.x, l.x); split_bf16(v01, h.y, l.y);
                *(__nv_bfloat162*)(Ch + (long long)r0 * ldc + n) = h;
                *(__nv_bfloat162*)(Cl + (long long)r0 * ldc + n) = l;
                split_bf16(v10, h.x, l.x); split_bf16(v11, h.y, l.y);
                *(__nv_bfloat162*)(Ch + (long long)r1 * ldc + n) = h;
                *(__nv_bfloat162*)(Cl + (long long)r1 * ldc + n) = l;
            } else { // OUT == 3
                int nl = n & 511;
                if (seg < 2) {
                    __nv_bfloat162 h, l;
                    split_bf16(v00, h.x, l.x); split_bf16(v01, h.y, l.y);
                    *(__nv_bfloat162*)(Xh + (long long)r0 * DMODEL + nl) = h;
                    *(__nv_bfloat162*)(Xl + (long long)r0 * DMODEL + nl) = l;
                    split_bf16(v10, h.x, l.x); split_bf16(v11, h.y, l.y);
                    *(__nv_bfloat162*)(Xh + (long long)r1 * DMODEL + nl) = h;
                    *(__nv_bfloat162*)(Xl + (long long)r1 * DMODEL + nl) = l;
                } else {
                    bf16 h, l;
                    split_bf16(v00, h, l); Xh[(long long)nl * TOKENS + r0] = h; Xl[(long long)nl * TOKENS + r0] = l;
                    split_bf16(v01, h, l); Xh[(long long)(nl + 1) * TOKENS + r0] = h; Xl[(long long)(nl + 1) * TOKENS + r0] = l;
                    split_bf16(v10, h, l); Xh[(long long)nl * TOKENS + r1] = h; Xl[(long long)nl * TOKENS + r1] = l;
                    split_bf16(v11, h, l); Xh[(long long)(nl + 1) * TOKENS + r1] = h; Xl[(long long)(nl + 1) * TOKENS + r1] = l;
                }
            }
        }
    }
}

#define GSMEM ((2 * (128 * 20) + 2 * (128 * 20)) * 2 * 4)

// ---------------- fused flash attention: 2 Q-tiles per CTA ----------------
// grid (8, 32): CTA handles q-tiles qt and qt+8 of one (b,h); K/V smem stages
// shared by both Q-sets (halves K/V global traffic, single-wave grid).
// Q fragments loaded directly global->registers (no Q smem).
#define FMW (64 * 36)
#define FSMEM2 (8 * FMW * 4)   // 73728 B: 2 stages x (Kh,Kl,Vh,Vl)

__global__ __launch_bounds__(128) void flash_k(
    const bf16* __restrict__ qh_, const bf16* __restrict__ ql_,
    const bf16* __restrict__ kh_, const bf16* __restrict__ kl_,
    const bf16* __restrict__ vTh_, const bf16* __restrict__ vTl_,
    bf16* __restrict__ oh_, bf16* __restrict__ ol_)
{
    extern __shared__ uint32_t sm[];
    const int qt = blockIdx.x;             // 0..7 -> tiles qt, qt+8
    const int bh = blockIdx.y;
    const int b = bh >> 3, h = bh & 7;
    const int t = threadIdx.x, lane = t & 31, w = t >> 5;
    const unsigned sb = (unsigned)__cvta_generic_to_shared(sm);

    auto load_stage = [&](int ti, int st) {
        const unsigned base = sb + st * 4 * FMW * 4;
        const int t0 = ti * 64;
        #pragma unroll
        for (int i = 0; i < 4; i++) {
            int id = i * 128 + t;
            int r = id >> 3, cb = id & 7;
            unsigned so = r * 144 + cb * 16;
            long long gk = ((long long)(b * SEQ + t0 + r)) * DMODEL + h * DHEAD + cb * 8;
            cpasync16(base + so, kh_ + gk);
            cpasync16(base + FMW * 4 + so, kl_ + gk);
            long long gv = ((long long)(h * DHEAD + r)) * TOKENS + b * SEQ + t0 + cb * 8;
            cpasync16(base + 2 * FMW * 4 + so, vTh_ + gv);
            cpasync16(base + 3 * FMW * 4 + so, vTl_ + gv);
        }
        asm volatile("cp.async.commit_group;");
    };

    load_stage(0, 0);

    // ---- Q fragments for both tile-sets, direct from global ----
    uint32_t qfh[2][4][4], qfl[2][4][4];
    #pragma unroll
    for (int set = 0; set < 2; set++) {
        int q0 = (qt + set * 8) * 64;
        long long rb = ((long long)(b * SEQ + q0 + w * 16 + (lane >> 2))) * DMODEL
                     + h * DHEAD + 2 * (lane & 3);
        #pragma unroll
        for (int ks = 0; ks < 4; ks++) {
            qfh[set][ks][0] = *(const uint32_t*)(qh_ + rb + ks * 16);
            qfh[set][ks][1] = *(const uint32_t*)(qh_ + rb + 8 * DMODEL + ks * 16);
            qfh[set][ks][2] = *(const uint32_t*)(qh_ + rb + ks * 16 + 8);
            qfh[set][ks][3] = *(const uint32_t*)(qh_ + rb + 8 * DMODEL + ks * 16 + 8);
            qfl[set][ks][0] = *(const uint32_t*)(ql_ + rb + ks * 16);
            qfl[set][ks][1] = *(const uint32_t*)(ql_ + rb + 8 * DMODEL + ks * 16);
            qfl[set][ks][2] = *(const uint32_t*)(ql_ + rb + ks * 16 + 8);
            qfl[set][ks][3] = *(const uint32_t*)(ql_ + rb + 8 * DMODEL + ks * 16 + 8);
        }
    }

    float acc_o[2][8][4];
    float mx[2][2], lsum[2][2];
    #pragma unroll
    for (int set = 0; set < 2; set++) {
        #pragma unroll
        for (int j = 0; j < 8; j++)
            #pragma unroll
            for (int r = 0; r < 4; r++) acc_o[set][j][r] = 0.f;
        mx[set][0] = -1e30f; mx[set][1] = -1e30f;
        lsum[set][0] = 0.f;  lsum[set][1] = 0.f;
    }

    asm volatile("cp.async.wait_group 0;" ::: "memory");
    __syncthreads();

    const int NT = SEQ / 64;

    for (int ti = 0; ti < NT; ti++) {
        if (ti + 1 < NT) load_stage(ti + 1, (ti + 1) & 1);

        const uint32_t* Kh = sm + (ti & 1) * 4 * FMW;
        const uint32_t* Kl = Kh + FMW;
        const uint32_t* Vh = Kh + 2 * FMW;
        const uint32_t* Vl = Kh + 3 * FMW;

        #pragma unroll
        for (int set = 0; set < 2; set++) {
            // ---- S = Q K^T (hi/lo triple) ----
            float s_[8][4];
            #pragma unroll
            for (int j = 0; j < 8; j++)
                #pragma unroll
                for (int r = 0; r < 4; r++) s_[j][r] = 0.f;

            #pragma unroll
            for (int ks = 0; ks < 4; ks++) {
                #pragma unroll
                for (int j = 0; j < 8; j++) {
                    int bi = (j * 8 + (lane >> 2)) * 36 + ks * 8 + (lane & 3);
                    uint32_t kb0 = Kh[bi], kb1 = Kh[bi + 4];
                    uint32_t kl0 = Kl[bi], kl1 = Kl[bi + 4];
                    MMA_BF16(s_[j], qfh[set][ks][0], qfh[set][ks][1], qfh[set][ks][2], qfh[set][ks][3], kb0, kb1);
                    MMA_BF16(s_[j], qfh[set][ks][0], qfh[set][ks][1], qfh[set][ks][2], qfh[set][ks][3], kl0, kl1);
                    MMA_BF16(s_[j], qfl[set][ks][0], qfl[set][ks][1], qfl[set][ks][2], qfl[set][ks][3], kb0, kb1);
                }
            }

            // ---- online softmax ----
            float tm0 = -1e30f, tm1 = -1e30f;
            #pragma unroll
            for (int j = 0; j < 8; j++) {
                s_[j][0] *= 0.125f; s_[j][1] *= 0.125f; s_[j][2] *= 0.125f; s_[j][3] *= 0.125f;
                tm0 = fmaxf(tm0, fmaxf(s_[j][0], s_[j][1]));
                tm1 = fmaxf(tm1, fmaxf(s_[j][2], s_[j][3]));
            }
            tm0 = fmaxf(tm0, __shfl_xor_sync(0xffffffffu, tm0, 1));
            tm0 = fmaxf(tm0, __shfl_xor_sync(0xffffffffu, tm0, 2));
            tm1 = fmaxf(tm1, __shfl_xor_sync(0xffffffffu, tm1, 1));
            tm1 = fmaxf(tm1, __shfl_xor_sync(0xffffffffu, tm1, 2));
            float mn0 = fmaxf(mx[set][0], tm0), mn1 = fmaxf(mx[set][1], tm1);
            float f0 = __expf(mx[set][0] - mn0), f1 = __expf(mx[set][1] - mn1);
            mx[set][0] = mn0; mx[set][1] = mn1;

            float sum0 = 0.f, sum1 = 0.f;
            #pragma unroll
            for (int j = 0; j < 8; j++) {
                s_[j][0] = __expf(s_[j][0] - mn0);
                s_[j][1] = __expf(s_[j][1] - mn0);
                s_[j][2] = __expf(s_[j][2] - mn1);
                s_[j][3] = __expf(s_[j][3] - mn1);
                sum0 += s_[j][0] + s_[j][1];
                sum1 += s_[j][2] + s_[j][3];
            }
            sum0 += __shfl_xor_sync(0xffffffffu, sum0, 1);
            sum0 += __shfl_xor_sync(0xffffffffu, sum0, 2);
            sum1 += __shfl_xor_sync(0xffffffffu, sum1, 1);
            sum1 += __shfl_xor_sync(0xffffffffu, sum1, 2);
            lsum[set][0] = lsum[set][0] * f0 + sum0;
            lsum[set][1] = lsum[set][1] * f1 + sum1;

            #pragma unroll
            for (int j = 0; j < 8; j++) {
                acc_o[set][j][0] *= f0; acc_o[set][j][1] *= f0;
                acc_o[set][j][2] *= f1; acc_o[set][j][3] *= f1;
            }

            // ---- O += P V (P split hi/lo in registers) ----
            #pragma unroll
            for (int ts = 0; ts < 4; ts++) {
                uint32_t pah[4], pal[4];
                #pragma unroll
                for (int half = 0; half < 2; half++) {
                    const float* p = s_[2 * ts + half];
                    __nv_bfloat162 h2, l2;
                    split_bf16(p[0], h2.x, l2.x); split_bf16(p[1], h2.y, l2.y);
                    pah[half ? 2 : 0] = *(uint32_t*)&h2;
                    pal[half ? 2 : 0] = *(uint32_t*)&l2;
                    split_bf16(p[2], h2.x, l2.x); split_bf16(p[3], h2.y, l2.y);
                    pah[half ? 3 : 1] = *(uint32_t*)&h2;
                    pal[half ? 3 : 1] = *(uint32_t*)&l2;
                }
                #pragma unroll
                for (int jd = 0; jd < 8; jd++) {
                    int bi = (jd * 8 + (lane >> 2)) * 36 + ts * 8 + (lane & 3);
                    uint32_t vb0 = Vh[bi], vb1 = Vh[bi + 4];
                    uint32_t vl0 = Vl[bi], vl1 = Vl[bi + 4];
                    MMA_BF16(acc_o[set][jd], pah[0], pah[1], pah[2], pah[3], vb0, vb1);
                    MMA_BF16(acc_o[set][jd], pah[0], pah[1], pah[2], pah[3], vl0, vl1);
                    MMA_BF16(acc_o[set][jd], pal[0], pal[1], pal[2], pal[3], vb0, vb1);
                }
            }
        }

        if (ti + 1 < NT) { asm volatile("cp.async.wait_group 0;" ::: "memory"); }
        __syncthreads();
    }

    // ---- epilogue: normalize, split hi/lo, store in bugged layout ----
    #pragma unroll
    for (int set = 0; set < 2; set++) {
        float i0 = 1.f / lsum[set][0], i1 = 1.f / lsum[set][1];
        int q0 = (qt + set * 8) * 64;
        int r0 = q0 + w * 16 + (lane >> 2);
        int r1 = r0 + 8;
        long long base0 = ((long long)bh * SEQ + r0) * DHEAD;
        long long base1 = ((long long)bh * SEQ + r1) * DHEAD;
        #pragma unroll
        for (int jd = 0; jd < 8; jd++) {
            int c = jd * 8 + 2 * (lane & 3);
            __nv_bfloat162 h2, l2;
            split_bf16(acc_o[set][jd][0] * i0, h2.x, l2.x);
            split_bf16(acc_o[set][jd][1] * i0, h2.y, l2.y);
            *(__nv_bfloat162*)(oh_ + base0 + c) = h2;
            *(__nv_bfloat162*)(ol_ + base0 + c) = l2;
            split_bf16(acc_o[set][jd][2] * i1, h2.x, l2.x);
            split_bf16(acc_o[set][jd][3] * i1, h2.y, l2.y);
            *(__nv_bfloat162*)(oh_ + base1 + c) = h2;
            *(__nv_bfloat162*)(ol_ + base1 + c) = l2;
        }
    }
}

// ---------------- fused residual add + LayerNorm (optionally emits hi/lo) ----------
template<bool WH>
__global__ void addln_k(const float* __restrict__ a, const float* __restrict__ b,
                        const float* __restrict__ g, const float* __restrict__ be,
                        float* __restrict__ o, bf16* __restrict__ oh, bf16* __restrict__ ol) {
    long long row = blockIdx.x;
    int t = threadIdx.x;
    float4 av = *(const float4*)(a + row * DMODEL + t * 4);
    float4 bv = *(const float4*)(b + row * DMODEL + t * 4);
    float x0 = av.x + bv.x, x1 = av.y + bv.y, x2 = av.z + bv.z, x3 = av.w + bv.w;
    float m = block_sum(x0 + x1 + x2 + x3) * (1.f / DMODEL);
    float d0 = x0 - m, d1 = x1 - m, d2 = x2 - m, d3 = x3 - m;
    float var = block_sum(d0 * d0 + d1 * d1 + d2 * d2 + d3 * d3) * (1.f / DMODEL);
    float r = rsqrtf(var + LN_EPS);
    float4 gv = *(const float4*)(g + t * 4);
    float4 ev = *(const float4*)(be + t * 4);
    float4 ov;
    ov.x = d0 * r * gv.x + ev.x;
    ov.y = d1 * r * gv.y + ev.y;
    ov.z = d2 * r * gv.z + ev.z;
    ov.w = d3 * r * gv.w + ev.w;
    *(float4*)(o + row * DMODEL + t * 4) = ov;
    if (WH) {
        __nv_bfloat162 h0, l0, h1, l1;
        split_bf16(ov.x, h0.x, l0.x); split_bf16(ov.y, h0.y, l0.y);
        split_bf16(ov.z, h1.x, l1.x); split_bf16(ov.w, h1.y, l1.y);
        long long off = row * DMODEL + t * 4;
        *(__nv_bfloat162*)(oh + off) = h0; *(__nv_bfloat162*)(oh + off + 2) = h1;
        *(__nv_bfloat162*)(ol + off) = l0; *(__nv_bfloat162*)(ol + off + 2) = l1;
    }
}

// ---------------- launch ----------------
extern "C" void kernel_launch(void* const* d_in, const int* in_sizes, int n_in,
                              void* d_out, int out_size)
{
    const int*   tok = (const int*)d_in[0];
    const float* emb = (const float*)d_in[1];
    const float* Wq = (const float*)d_in[2],  *bq = (const float*)d_in[3];
    const float* Wk = (const float*)d_in[4],  *bk = (const float*)d_in[5];
    const float* Wv = (const float*)d_in[6],  *bv = (const float*)d_in[7];
    const float* Wo = (const float*)d_in[8],  *bo = (const float*)d_in[9];
    const float* W1 = (const float*)d_in[10], *b1 = (const float*)d_in[11];
    const float* W2 = (const float*)d_in[12], *b2 = (const float*)d_in[13];
    const float* lg = (const float*)d_in[14], *lb = (const float*)d_in[15];
    float* out = (float*)d_out;

    float *x, *y, *bqkv;
    bf16 *xh, *xl, *qh, *ql, *kh, *kl, *vTh, *vTl, *ah, *al, *h1h, *h1l;
    bf16 *wqkvTh, *wqkvTl, *woTh, *woTl, *w1Th, *w1Tl, *w2Th, *w2Tl;
    cudaGetSymbolAddress((void**)&x,   g_x);
    cudaGetSymbolAddress((void**)&y,   g_y);
    cudaGetSymbolAddress((void**)&bqkv, g_bqkv);
    cudaGetSymbolAddress((void**)&xh,  g_xh);   cudaGetSymbolAddress((void**)&xl,  g_xl);
    cudaGetSymbolAddress((void**)&qh,  g_qh);   cudaGetSymbolAddress((void**)&ql,  g_ql);
    cudaGetSymbolAddress((void**)&kh,  g_kh);   cudaGetSymbolAddress((void**)&kl,  g_kl);
    cudaGetSymbolAddress((void**)&vTh, g_vTh);  cudaGetSymbolAddress((void**)&vTl, g_vTl);
    cudaGetSymbolAddress((void**)&ah,  g_ah);   cudaGetSymbolAddress((void**)&al,  g_al);
    cudaGetSymbolAddress((void**)&h1h, g_h1h);  cudaGetSymbolAddress((void**)&h1l, g_h1l);
    cudaGetSymbolAddress((void**)&wqkvTh, g_wqkvTh); cudaGetSymbolAddress((void**)&wqkvTl, g_wqkvTl);
    cudaGetSymbolAddress((void**)&woTh, g_woTh); cudaGetSymbolAddress((void**)&woTl, g_woTl);
    cudaGetSymbolAddress((void**)&w1Th, g_w1Th); cudaGetSymbolAddress((void**)&w1Tl, g_w1Tl);
    cudaGetSymbolAddress((void**)&w2Th, g_w2Th); cudaGetSymbolAddress((void**)&w2Tl, g_w2Tl);

    cudaFuncSetAttribute(gemm_k<0,false>, cudaFuncAttributeMaxDynamicSharedMemorySize, GSMEM);
    cudaFuncSetAttribute(gemm_k<1,true >, cudaFuncAttributeMaxDynamicSharedMemorySize, GSMEM);
    cudaFuncSetAttribute(gemm_k<3,false>, cudaFuncAttributeMaxDynamicSharedMemorySize, GSMEM);
    cudaFuncSetAttribute(flash_k, cudaFuncAttributeMaxDynamicSharedMemorySize, FSMEM2);

    // ---- setup: exactly 5 launches so launch index 5 = first QKV GEMM (ncu -s 5) ----
    dim3 cb(32, 8);
    wconv4_k<<<dim3(16, 16, 4 * NLAYERS), cb>>>(Wq, Wk, Wv, Wo, wqkvTh, wqkvTl, woTh, woTl);
    wconv_k<<<dim3(64, 16, NLAYERS), cb>>>(W1, w1Th, w1Tl, DFF, DMODEL,
                                           (long long)DMODEL*DFF, (long long)DMODEL*DFF);
    wconv_k<<<dim3(16, 64, NLAYERS), cb>>>(W2, w2Th, w2Tl, DMODEL, DFF,
                                           (long long)DMODEL*DFF, (long long)DMODEL*DFF);
    bmerge_k<<<NLAYERS, DMODEL>>>(bq, bk, bv, bqkv);
    embed_k<<<TOKENS, 128>>>(tok, emb, x, xh, xl);

    for (int i = 0; i < NLAYERS; i++) {
        long long woff = (long long)i * DMODEL * DMODEL;
        long long qoff = (long long)i * NQKV * DMODEL;
        long long foff = (long long)i * DMODEL * DFF;
        const float* boi = bo + (long long)i * DMODEL;
        const float* b1i = b1 + (long long)i * DFF;
        const float* b2i = b2 + (long long)i * DMODEL;
        const float* lgi = lg + (long long)i * DMODEL;
        const float* lbi = lb + (long long)i * DMODEL;

        // merged QKV projection: N=1536; Q,K row-major; V transposed
        gemm_k<3,false><<<dim3(12, 32), 128, GSMEM>>>(
            xh, xl, DMODEL, wqkvTh + qoff, wqkvTl + qoff, DMODEL,
            nullptr, qh, ql, kh, kl, vTh, vTl, DMODEL,
            bqkv + (long long)i * NQKV, DMODEL);

        // fused attention (2 Q-tiles/CTA) -> bf16 hi/lo attn in bugged layout
        flash_k<<<dim3(8, 32), 128, FSMEM2>>>(qh, ql, kh, kl, vTh, vTl, ah, al);

        // O projection -> fp32 y
        gemm_k<0,false><<<dim3(4, 32), 128, GSMEM>>>(
            ah, al, DMODEL, woTh + woff, woTl + woff, DMODEL,
            y, nullptr, nullptr, nullptr, nullptr, nullptr, nullptr, DMODEL,
            boi, DMODEL);

        addln_k<true><<<TOKENS, 128>>>(x, y, lgi, lbi, x, xh, xl);

        // FFN1 (relu) -> bf16 hi/lo [4096][2048]
        gemm_k<1,true><<<dim3(16, 32), 128, GSMEM>>>(
            xh, xl, DMODEL, w1Th + foff, w1Tl + foff, DMODEL,
            nullptr, h1h, h1l, nullptr, nullptr, nullptr, nullptr, DFF,
            b1i, DMODEL);

        // FFN2 -> fp32 y
        gemm_k<0,false><<<dim3(4, 32), 128, GSMEM>>>(
            h1h, h1l, DFF, w2Th + foff, w2Tl + foff, DFF,
            y, nullptr, nullptr, nullptr, nullptr, nullptr, nullptr, DMODEL,
            b2i, DFF);

        if (i == NLAYERS - 1)
            addln_k<false><<<TOKENS, 128>>>(x, y, lgi, lbi, out, nullptr, nullptr);
        else
            addln_k<true><<<TOKENS, 128>>>(x, y, lgi, lbi, x, xh, xl);
    }
}